// round 2
// baseline (speedup 1.0000x reference)
#include <cuda_runtime.h>
#include <math.h>

#define N_ROWS 65536

// ---------------- scratch (device globals: allowed; no allocations) ----------------
__device__ float g_scal[(size_t)N_ROWS * 384];
__device__ float g_h   [(size_t)N_ROWS * 384];
__device__ float g_g   [(size_t)N_ROWS * 768];
__device__ float g_s   [(size_t)N_ROWS * 128];
__device__ float g_v   [(size_t)N_ROWS * 384];

__device__ __forceinline__ float silu_f(float x) {
    return x / (1.0f + __expf(-x));
}

// ---------------- build scal = [s, s*s, |v|^2/sqrt(3)] ----------------
__global__ void build_scal_kernel(const float* __restrict__ sp, int ss,
                                  const float* __restrict__ vp, int vs,
                                  float* __restrict__ scal)
{
    int idx = blockIdx.x * blockDim.x + threadIdx.x;   // N_ROWS*128 threads
    int n = idx >> 7;
    int j = idx & 127;
    float s  = sp[(size_t)n * ss + j];
    const float* vr = vp + (size_t)n * vs + 3 * j;
    float vx = vr[0], vy = vr[1], vz = vr[2];
    float* row = scal + (size_t)n * 384;
    row[j]       = s;
    row[128 + j] = s * s;
    row[256 + j] = (vx*vx + vy*vy + vz*vz) * 0.5773502691896258f; // 1/sqrt(3)
}

// ---------------- generic 128x128x8 fp32 GEMM, 3 fused modes ----------------
// MODE 0: C = silu(A @ B * scale)                          (h and g layers)
// MODE 1: C = Sin + (A .* G[:, :384]) @ B * scale          (ys + residual)
// MODE 2: C = Vin + (vecc .* G[:, 384:640]) @ B * scale    (yv + residual, c = blockIdx.z)
//         vecc[n,m] = (m<128) ? Vin[n,m,c] : Sin[n,m-128]*Vin[n,m-128,c]
#define BM 128
#define BN 128
#define BK 8

template<int MODE>
__global__ __launch_bounds__(256, 2)
void gemm_tpl(const float* __restrict__ A, int lda,
              const float* __restrict__ G,
              const float* __restrict__ Vin, int ldv,
              const float* __restrict__ Sin, int lds_,
              const float* __restrict__ B,
              float* __restrict__ C, int ldc,
              int K, int M, float scale)
{
    __shared__ float As[BK][BM];
    __shared__ float Bs[BK][BN];

    const int tid  = threadIdx.x;
    const int row0 = blockIdx.y * BM;
    const int col0 = blockIdx.x * BN;
    const int c    = (MODE == 2) ? blockIdx.z : 0;

    const int ar = tid >> 1;          // 0..127 : A row within tile
    const int ak = (tid & 1) * 4;     // 0 or 4 : A k offset
    const int br = tid >> 5;          // 0..7   : B k row
    const int bc = (tid & 31) * 4;    // 0..124 : B col

    const int tx = tid & 15;          // 16 col-groups
    const int ty = tid >> 4;          // 16 row-groups

    float acc[8][8];
#pragma unroll
    for (int i = 0; i < 8; i++)
#pragma unroll
        for (int j = 0; j < 8; j++) acc[i][j] = 0.0f;

    const int arow = row0 + ar;

    for (int k0 = 0; k0 < K; k0 += BK) {
        // ---- stage global -> regs ----
        float a[4];
        const int kk0 = k0 + ak;
        if (MODE == 0) {
            float4 av = *(const float4*)(A + (size_t)arow * lda + kk0);
            a[0] = av.x; a[1] = av.y; a[2] = av.z; a[3] = av.w;
        } else if (MODE == 1) {
            float4 av = *(const float4*)(A + (size_t)arow * lda + kk0);
            float4 gv = *(const float4*)(G + (size_t)arow * 768 + kk0);
            a[0] = av.x * gv.x; a[1] = av.y * gv.y;
            a[2] = av.z * gv.z; a[3] = av.w * gv.w;
        } else {
            const float* grow = G + (size_t)arow * 768 + 384;
#pragma unroll
            for (int q = 0; q < 4; q++) {
                int m = kk0 + q;
                float base;
                if (m < 128) {
                    base = Vin[(size_t)arow * ldv + m * 3 + c];
                } else {
                    int mm = m - 128;
                    base = Sin[(size_t)arow * lds_ + mm] *
                           Vin[(size_t)arow * ldv + mm * 3 + c];
                }
                a[q] = grow[m] * base;
            }
        }
        float4 bv = *(const float4*)(B + (size_t)(k0 + br) * M + col0 + bc);

        __syncthreads();   // previous tile fully consumed
        As[ak + 0][ar] = a[0];
        As[ak + 1][ar] = a[1];
        As[ak + 2][ar] = a[2];
        As[ak + 3][ar] = a[3];
        *(float4*)&Bs[br][bc] = bv;
        __syncthreads();

        // ---- compute 8x8 per thread ----
#pragma unroll
        for (int kk = 0; kk < BK; kk++) {
            float ra[8], rb[8];
            float4 a0 = *(const float4*)&As[kk][ty * 8];
            float4 a1 = *(const float4*)&As[kk][ty * 8 + 4];
            ra[0]=a0.x; ra[1]=a0.y; ra[2]=a0.z; ra[3]=a0.w;
            ra[4]=a1.x; ra[5]=a1.y; ra[6]=a1.z; ra[7]=a1.w;
            float4 b0 = *(const float4*)&Bs[kk][tx * 4];
            float4 b1 = *(const float4*)&Bs[kk][64 + tx * 4];
            rb[0]=b0.x; rb[1]=b0.y; rb[2]=b0.z; rb[3]=b0.w;
            rb[4]=b1.x; rb[5]=b1.y; rb[6]=b1.z; rb[7]=b1.w;
#pragma unroll
            for (int i = 0; i < 8; i++)
#pragma unroll
                for (int j = 0; j < 8; j++)
                    acc[i][j] = fmaf(ra[i], rb[j], acc[i][j]);
        }
    }

    // ---- epilogue ----
#pragma unroll
    for (int i = 0; i < 8; i++) {
        const int r = row0 + ty * 8 + i;
        if (MODE == 0) {
            float4 o0, o1;
            o0.x = silu_f(acc[i][0]*scale); o0.y = silu_f(acc[i][1]*scale);
            o0.z = silu_f(acc[i][2]*scale); o0.w = silu_f(acc[i][3]*scale);
            o1.x = silu_f(acc[i][4]*scale); o1.y = silu_f(acc[i][5]*scale);
            o1.z = silu_f(acc[i][6]*scale); o1.w = silu_f(acc[i][7]*scale);
            *(float4*)(C + (size_t)r * ldc + col0 + tx * 4)      = o0;
            *(float4*)(C + (size_t)r * ldc + col0 + 64 + tx * 4) = o1;
        } else if (MODE == 1) {
            float4 s0 = *(const float4*)(Sin + (size_t)r * lds_ + col0 + tx * 4);
            float4 s1 = *(const float4*)(Sin + (size_t)r * lds_ + col0 + 64 + tx * 4);
            float4 o0, o1;
            o0.x = s0.x + acc[i][0]*scale; o0.y = s0.y + acc[i][1]*scale;
            o0.z = s0.z + acc[i][2]*scale; o0.w = s0.w + acc[i][3]*scale;
            o1.x = s1.x + acc[i][4]*scale; o1.y = s1.y + acc[i][5]*scale;
            o1.z = s1.z + acc[i][6]*scale; o1.w = s1.w + acc[i][7]*scale;
            *(float4*)(C + (size_t)r * ldc + col0 + tx * 4)      = o0;
            *(float4*)(C + (size_t)r * ldc + col0 + 64 + tx * 4) = o1;
        } else {
#pragma unroll
            for (int j = 0; j < 8; j++) {
                int cc = col0 + tx * 4 + (j & 3) + (j >> 2) * 64;
                float res = Vin[(size_t)r * ldv + cc * 3 + c];
                C[(size_t)r * ldc + cc * 3 + c] = res + acc[i][j] * scale;
            }
        }
    }
}

// ---------------- equivariant layernorm (in place), one block per row ----------------
__device__ __forceinline__ float block_sum_128(float x, float* red)
{
#pragma unroll
    for (int o = 16; o; o >>= 1) x += __shfl_xor_sync(0xffffffffu, x, o);
    int t = threadIdx.x;
    if ((t & 31) == 0) red[t >> 5] = x;
    __syncthreads();
    float tot = red[0] + red[1] + red[2] + red[3];
    __syncthreads();
    return tot;
}

__global__ void ln_kernel(float* __restrict__ s, float* __restrict__ v)
{
    __shared__ float red[4];
    int n = blockIdx.x;
    int t = threadIdx.x;   // 128 threads

    float sv = s[(size_t)n * 128 + t];
    float* vr = v + (size_t)n * 384 + 3 * t;
    float vx = vr[0], vy = vr[1], vz = vr[2];

    float sum  = block_sum_128(sv, red);
    float sum2 = block_sum_128(sv * sv, red);
    float vsum = block_sum_128(vx*vx + vy*vy + vz*vz, red);

    float mu  = sum * (1.0f / 128.0f);
    float var = sum2 * (1.0f / 128.0f) - mu * mu;
    float inv_sd = rsqrtf(var + 1e-6f);
    s[(size_t)n * 128 + t] = (sv - mu) * inv_sd;

    float inv_vs = rsqrtf(vsum * (1.0f / 384.0f) + 1e-6f);
    vr[0] = vx * inv_vs;
    vr[1] = vy * inv_vs;
    vr[2] = vz * inv_vs;
}

// ---------------- launcher ----------------
extern "C" void kernel_launch(void* const* d_in, const int* in_sizes, int n_in,
                              void* d_out, int out_size)
{
    const float* x    = (const float*)d_in[0];
    // d_in[1] mask (unused, all ones), d_in[2] coord (unused by reference)
    const float* W1_0 = (const float*)d_in[3];
    const float* W2_0 = (const float*)d_in[4];
    const float* Ws_0 = (const float*)d_in[5];
    const float* Wv_0 = (const float*)d_in[6];
    const float* W1_1 = (const float*)d_in[7];
    const float* W2_1 = (const float*)d_in[8];
    const float* Ws_1 = (const float*)d_in[9];
    const float* Wv_1 = (const float*)d_in[10];
    float* out = (float*)d_out;

    // Resolve scratch symbol addresses once per process (pure lookups, no
    // allocation, deterministic). Cached so the captured region contains
    // only kernel launches after the first call.
    static float *scal = nullptr, *h = nullptr, *g = nullptr, *s = nullptr, *v = nullptr;
    if (!scal) {
        cudaGetSymbolAddress((void**)&scal, g_scal);
        cudaGetSymbolAddress((void**)&h,    g_h);
        cudaGetSymbolAddress((void**)&g,    g_g);
        cudaGetSymbolAddress((void**)&s,    g_s);
        cudaGetSymbolAddress((void**)&v,    g_v);
    }

    const float SC384 = 0.051031036307982884f;  // 1/sqrt(384)
    const float SC256 = 0.0625f;                // 1/sqrt(256)
    const int   RB    = N_ROWS / BM;            // 512 row tiles

    // ================= block 0 (inputs from x) =================
    build_scal_kernel<<<N_ROWS * 128 / 256, 256>>>(x, 512, x + 128, 512, scal);
    gemm_tpl<0><<<dim3(3, RB), 256>>>(scal, 384, nullptr, nullptr, 0, nullptr, 0,
                                      W1_0, h, 384, 384, 384, SC384);
    gemm_tpl<0><<<dim3(6, RB), 256>>>(h, 384, nullptr, nullptr, 0, nullptr, 0,
                                      W2_0, g, 768, 384, 768, SC384);
    gemm_tpl<1><<<dim3(1, RB), 256>>>(scal, 384, g, nullptr, 0, x, 512,
                                      Ws_0, s, 128, 384, 128, SC384);
    gemm_tpl<2><<<dim3(1, RB, 3), 256>>>(nullptr, 0, g, x + 128, 512, x, 512,
                                         Wv_0, v, 384, 256, 128, SC256);
    ln_kernel<<<N_ROWS, 128>>>(s, v);

    // ================= block 1 (inputs from s/v, outputs to d_out) =================
    build_scal_kernel<<<N_ROWS * 128 / 256, 256>>>(s, 128, v, 384, scal);
    gemm_tpl<0><<<dim3(3, RB), 256>>>(scal, 384, nullptr, nullptr, 0, nullptr, 0,
                                      W1_1, h, 384, 384, 384, SC384);
    gemm_tpl<0><<<dim3(6, RB), 256>>>(h, 384, nullptr, nullptr, 0, nullptr, 0,
                                      W2_1, g, 768, 384, 768, SC384);
    gemm_tpl<1><<<dim3(1, RB), 256>>>(scal, 384, g, nullptr, 0, s, 128,
                                      Ws_1, out, 512, 384, 128, SC384);
    gemm_tpl<2><<<dim3(1, RB, 3), 256>>>(nullptr, 0, g, v, 384, s, 128,
                                         Wv_1, out + 128, 512, 256, 128, SC256);
}